// round 13
// baseline (speedup 1.0000x reference)
#include <cuda_runtime.h>
#include <math.h>

#define BATCH   8
#define NA      8732
#define NAP     8736
#define NC      21
#define NFG     20
#define TOPK    200
#define PRE     1024
#define DCAP    1280
#define FBINS   2048
#define FSH     12
#define BASEB   0x3F000000u
#define CONF_T  0.5f
#define FULLM   0xFFFFFFFFu

// Exact midpoint for  div.rn.f32(inter,union) > 0.45f :
// 0.45f = 0x3EE66666 (even mantissa); ulp = 2^-25; midpoint = c + 2^-26.
#define IOU_MID (0.449999988079071044921875 + 1.490116119384765625e-8)

// ---- scratch (static __device__, allocation-free) ----
__device__ float    g_clsT[BATCH * NFG * NAP];   // transposed scores; pad stays 0
__device__ float    g_kscore[BATCH * NFG * TOPK];
__device__ float4   g_kbox[BATCH * NFG * TOPK];
__device__ int      g_kcount[BATCH * NFG];
__device__ unsigned g_done[BATCH];               // wrap counters (stay 0 after run)

#define TR_TILE   128
#define TR_TPB    ((NA + TR_TILE - 1) / TR_TILE)   // 69
#define TR_BLOCKS (BATCH * TR_TPB)

// BIT-EXACT equivalent of  div.rn.f32(inter,uni) > 0.45f  (uni>0 always here):
// fp32 directed-rounding interval; exact double test only in the ~2-ulp gap.
//  inter > ru(c*uni)  =>  inter >= ru+ulp >= c*uni + 0.45*uni*2^-24 > MID*uni -> true
//  inter <= rd(c*uni) =>  inter <= c*uni < MID*uni                            -> false
__device__ __forceinline__ bool iou_hit(float4 p, float pa, float4 q, float qa) {
    float w = fminf(p.z, q.z) - fmaxf(p.x, q.x) + 1.0f;
    float h = fminf(p.w, q.w) - fmaxf(p.y, q.y) + 1.0f;
    float inter = fmaxf(w, 0.0f) * fmaxf(h, 0.0f);
    float uni = pa + qa - inter;
    float hi = __fmul_ru(0.45f, uni);
    float lo = __fmul_rd(0.45f, uni);
    if (inter > hi) return true;
    if (inter <= lo) return false;
    return (double)inter > IOU_MID * (double)uni;   // rare exact fallback
}

__device__ __forceinline__ unsigned finebin(unsigned bits) {
    unsigned fb = (bits - BASEB) >> FSH;
    return fb > (FBINS - 1u) ? (FBINS - 1u) : fb;
}

// Block suffix-scan over FBINS bins (512 threads, 4 consecutive bins each).
__device__ __forceinline__ int suffix_scan_2048(int* hist, int tid, int* sfx,
                                                int* above_out) {
    __shared__ int ws[16];
    __shared__ int s_total;
    const int lane = tid & 31, wid = tid >> 5;
    int b4 = tid * 4;
    int h0 = hist[b4], h1 = hist[b4 + 1], h2 = hist[b4 + 2], h3 = hist[b4 + 3];
    sfx[3] = h3; sfx[2] = h2 + sfx[3]; sfx[1] = h1 + sfx[2]; sfx[0] = h0 + sfx[1];
    int T = sfx[0], S = T;
#pragma unroll
    for (int off = 1; off < 32; off <<= 1) {
        int v = __shfl_down_sync(FULLM, S, off);
        if (lane + off < 32) S += v;
    }
    if (lane == 0) ws[wid] = S;
    __syncthreads();
    if (tid < 16) {
        int W = ws[tid];
#pragma unroll
        for (int off = 1; off < 16; off <<= 1) {
            int v = __shfl_down_sync(0x0000FFFFu, W, off);
            if (tid + off < 16) W += v;
        }
        ws[tid] = W;
        if (tid == 0) s_total = W;
    }
    __syncthreads();
    int above = ((wid < 15) ? ws[wid + 1] : 0) + (S - T);
    sfx[0] += above; sfx[1] += above; sfx[2] += above; sfx[3] += above;
    hist[b4]     = sfx[1];
    hist[b4 + 1] = sfx[2];
    hist[b4 + 2] = sfx[3];
    hist[b4 + 3] = above;
    *above_out = above;
    return s_total;
}

// ============================================================
// Kernel 1: transpose cls [b][a][c] -> g_clsT [b][c][a] (coalesced).
// ============================================================
__global__ void prep_kernel(const float* __restrict__ cls) {
    __shared__ float sh[TR_TILE * NC];
    int t = blockIdx.x;
    int b = t / TR_TPB, tile = t % TR_TPB;
    int a0 = tile * TR_TILE;
    int n = NA - a0; if (n > TR_TILE) n = TR_TILE;
    const float* src = cls + ((size_t)(b * NA + a0)) * NC;
    for (int i = threadIdx.x; i < n * NC; i += 256) sh[i] = src[i];
    __syncthreads();
    int half = threadIdx.x >> 7;
    int t2 = threadIdx.x & 127;
    if (t2 < n) {
        for (int c = half * 10; c < half * 10 + 10; ++c)
            g_clsT[((size_t)(b * NFG + c)) * NAP + a0 + t2] = sh[t2 * NC + c + 1];
    }
}

// ============================================================
// Kernel 2: bucket top-1024 + fixpoint greedy NMS; last CTA per image
// also performs the per-image global top-200 (fused). 512 threads.
// ============================================================
__global__ __launch_bounds__(512, 2) void nms_kernel(const float* __restrict__ loc,
                                                     const float* __restrict__ anch,
                                                     float* __restrict__ out) {
    const int bc  = blockIdx.x;
    const int b   = bc / NFG;
    const int c20 = bc % NFG;
    const int tid = threadIdx.x;

    __shared__ __align__(16) int histbuf[FBINS];             // 8KB
    __shared__ __align__(16) unsigned long long dest[DCAP];  // 10KB
    __shared__ __align__(16) float4 sbox[PRE];               // 16KB
    __shared__ float  sar[PRE], ssc[PRE];                    // 8KB
    __shared__ unsigned kw[8], pf[8];
    __shared__ int psum[8];
    __shared__ int skc[NFG];
    __shared__ int s_fl[2];
    __shared__ int s_ftb, s_sel, s_last;

    int* hist = histbuf;
    unsigned* colmask = (unsigned*)histbuf;
    float4* lbox = (float4*)dest;
    float*  lar  = (float*)(dest + 512);

    for (int i = tid; i < FBINS; i += 512) hist[i] = 0;
    if (tid == 0) { s_ftb = -1; s_sel = 0; }
    __syncthreads();

    const float4* scol4 = reinterpret_cast<const float4*>(
        g_clsT + ((size_t)(b * NFG + c20)) * NAP);

    // ---- A: fine histogram, vectorized float4 (pad scores are 0) ----
    for (int v = tid; v < NAP / 4; v += 512) {
        float4 s4 = scol4[v];
        if (s4.x > CONF_T) atomicAdd(&hist[finebin(__float_as_uint(s4.x))], 1);
        if (s4.y > CONF_T) atomicAdd(&hist[finebin(__float_as_uint(s4.y))], 1);
        if (s4.z > CONF_T) atomicAdd(&hist[finebin(__float_as_uint(s4.z))], 1);
        if (s4.w > CONF_T) atomicAdd(&hist[finebin(__float_as_uint(s4.w))], 1);
    }
    __syncthreads();

    // ---- B: suffix scan; unique-boundary threshold (no atomics) ----
    int sfx[4], above;
    int total = suffix_scan_2048(hist, tid, sfx, &above);
    {
        int need = total < PRE ? total : PRE;
        if (need > 0) {
#pragma unroll
            for (int q = 0; q < 4; ++q) {
                int nxt = (q < 3) ? sfx[q + 1] : above;
                if (sfx[q] >= need && nxt < need) {
                    s_ftb = tid * 4 + q;
                    s_sel = sfx[q];
                }
            }
        }
    }
    __syncthreads();
    const int ftb = s_ftb;
    int count = s_sel; if (count > PRE) count = PRE; if (count > DCAP) count = DCAP;

    // ---- C: scatter to exact positions + per-bin tie sort ----
    if (ftb >= 0) {
        for (int v = tid; v < NAP / 4; v += 512) {
            float4 s4 = scol4[v];
            float sv[4] = {s4.x, s4.y, s4.z, s4.w};
#pragma unroll
            for (int k = 0; k < 4; ++k) {
                if (sv[k] > CONF_T) {
                    unsigned bits = __float_as_uint(sv[k]);
                    int fb = (int)finebin(bits);
                    if (fb >= ftb) {
                        int pos = atomicAdd(&hist[fb], 1);
                        if (pos < DCAP)
                            dest[pos] = ((unsigned long long)bits << 32) |
                                        (unsigned)(65535 - (4 * v + k));
                    }
                }
            }
        }
        __syncthreads();
        for (int fb = ftb + tid; fb < FBINS; fb += 512) {
            int lo = (fb == FBINS - 1) ? 0 : hist[fb + 1];
            int hi = hist[fb];
            if (hi > DCAP) hi = DCAP;
            if (lo > hi) lo = hi;
            for (int x = lo + 1; x < hi; ++x) {
                unsigned long long key = dest[x];
                int y = x - 1;
                while (y >= lo && dest[y] < key) { dest[y + 1] = dest[y]; --y; }
                dest[y + 1] = key;
            }
        }
        __syncthreads();
    }

    // ---- E: decode candidate boxes best-first ----
    const float4* loc4  = reinterpret_cast<const float4*>(loc);
    const float4* anch4 = reinterpret_cast<const float4*>(anch);
#pragma unroll
    for (int t = 0; t < 2; ++t) {
        int r = tid + t * 512;
        if (r < count) {
            unsigned long long key = dest[r];
            int a = 65535 - (int)(key & 0xFFFFu);
            float4 l  = loc4[b * NA + a];
            float4 an = anch4[a];
            float cx = an.x + l.x * 0.1f * an.z;
            float cy = an.y + l.y * 0.1f * an.w;
            float w  = an.z * expf(l.z * 0.2f);
            float h  = an.w * expf(l.w * 0.2f);
            float x1 = cx - w * 0.5f;
            float y1 = cy - h * 0.5f;
            float4 bb;
            bb.x = fminf(fmaxf(x1 * 300.0f, 0.0f), 299.0f);
            bb.y = fminf(fmaxf(y1 * 300.0f, 0.0f), 299.0f);
            bb.z = fminf(fmaxf((x1 + w) * 300.0f, 0.0f), 299.0f);
            bb.w = fminf(fmaxf((y1 + h) * 300.0f, 0.0f), 299.0f);
            sbox[r] = bb;
            sar[r] = (bb.z - bb.x + 1.0f) * (bb.w - bb.y + 1.0f);
            ssc[r] = __uint_as_float((unsigned)(key >> 32));
        }
    }
    __syncthreads();   // hist & dest dead; overlays live

    // ---- F: tiled greedy NMS via parallel fixpoint ----
    int nL = 0;
    for (int base = 0; base < count && nL < TOPK; base += 256) {
        int m = count - base; if (m > 256) m = 256;
        if (tid < 8) pf[tid] = 0u;
        __syncthreads();
        // prefilter vs kept list: 2 threads per candidate, 4-wide batched
        if (base > 0 && nL > 0) {
            int i = tid >> 1, half = tid & 1;
            if (i < m) {
                float4 bb = sbox[base + i];
                float ab = sar[base + i];
                bool dead = false;
                int k = half;
                for (; k + 6 < nL; k += 8) {
                    dead |= iou_hit(lbox[k],     lar[k],     bb, ab);
                    dead |= iou_hit(lbox[k + 2], lar[k + 2], bb, ab);
                    dead |= iou_hit(lbox[k + 4], lar[k + 4], bb, ab);
                    dead |= iou_hit(lbox[k + 6], lar[k + 6], bb, ab);
                }
                for (; k < nL; k += 2)
                    dead |= iou_hit(lbox[k], lar[k], bb, ab);
                if (dead) atomicOr(&pf[i >> 5], 1u << (i & 31));
            }
        }
        // triangular IoU mask; lanes share w, consecutive i
#pragma unroll
        for (int q = 0; q < 4; ++q) {
            int jid = tid + q * 512;
            int i = jid & 255, w = jid >> 8;
            int jn = i - w * 32; if (jn > 32) jn = 32;
            if (i < m && jn > 0) {
                float4 bi = sbox[base + i];
                float ai = sar[base + i];
                unsigned bits = 0u;
                int j0 = base + w * 32;
                int l = 0;
                for (; l + 4 <= jn; l += 4) {
                    if (iou_hit(bi, ai, sbox[j0 + l],     sar[j0 + l]))     bits |= 1u << l;
                    if (iou_hit(bi, ai, sbox[j0 + l + 1], sar[j0 + l + 1])) bits |= 1u << (l + 1);
                    if (iou_hit(bi, ai, sbox[j0 + l + 2], sar[j0 + l + 2])) bits |= 1u << (l + 2);
                    if (iou_hit(bi, ai, sbox[j0 + l + 3], sar[j0 + l + 3])) bits |= 1u << (l + 3);
                }
                for (; l < jn; ++l)
                    if (iou_hit(bi, ai, sbox[j0 + l], sar[j0 + l]))
                        bits |= 1u << l;
                colmask[i * 8 + w] = bits;
            } else if (i < m) {
                colmask[i * 8 + w] = 0u;
            }
        }
        __syncthreads();
        if (tid < 8) {
            int lo = tid * 32;
            unsigned valid;
            if (m >= lo + 32)      valid = FULLM;
            else if (m <= lo)      valid = 0u;
            else                   valid = (1u << (m - lo)) - 1u;
            kw[tid] = valid & ~pf[tid];
        }
        if (tid == 0) { s_fl[0] = 0; s_fl[1] = 0; }
        // cache own colmask row + precondition in registers
        unsigned cm[8];
        int pre_ok = 0;
        __syncthreads();
        if (tid < m && !((pf[tid >> 5] >> (tid & 31)) & 1u)) {
            pre_ok = 1;
#pragma unroll
            for (int w = 0; w < 8; ++w) cm[w] = colmask[tid * 8 + w];
        }
        // fixpoint: 2 barriers per sweep, parity convergence flags
        int p = 0;
        for (;;) {
            int alive = 0;
            if (pre_ok) {
                unsigned acc = (cm[0] & kw[0]) | (cm[1] & kw[1]) |
                               (cm[2] & kw[2]) | (cm[3] & kw[3]) |
                               (cm[4] & kw[4]) | (cm[5] & kw[5]) |
                               (cm[6] & kw[6]) | (cm[7] & kw[7]);
                alive = (acc == 0u);
            }
            __syncthreads();                       // all reads of kw done
            unsigned nw = __ballot_sync(FULLM, alive);
            if (tid < 256 && (tid & 31) == 0) {
                if (nw != kw[tid >> 5]) s_fl[p] = 1;
                kw[tid >> 5] = nw;
            }
            if (tid == 0) s_fl[p ^ 1] = 0;
            __syncthreads();                       // kw + flags visible
            if (!s_fl[p]) break;
            p ^= 1;
        }
        if (tid < 8) {
            int s = 0;
            for (int w2 = 0; w2 < tid; ++w2) s += __popc(kw[w2]);
            psum[tid] = s;
        }
        __syncthreads();
        int nk = psum[7] + __popc(kw[7]);
        int take = TOPK - nL; if (take > nk) take = nk;
        if (tid < m && ((kw[tid >> 5] >> (tid & 31)) & 1u)) {
            int r = psum[tid >> 5] + __popc(kw[tid >> 5] & ((1u << (tid & 31)) - 1u));
            if (r < take) {
                int slot = nL + r;
                int gb = bc * TOPK + slot;
                g_kscore[gb] = ssc[base + tid];
                g_kbox[gb]   = sbox[base + tid];
                lbox[slot]   = sbox[base + tid];
                lar[slot]    = sar[base + tid];
            }
        }
        nL += take;
        __syncthreads();
    }
    if (tid == 0) g_kcount[bc] = nL;

    // ---- G: completion counter; last CTA of image runs the global top-200 ----
    if (tid == 0) {
        __threadfence();
        unsigned old = atomicInc(&g_done[b], NFG - 1);
        s_last = (old == NFG - 1);
    }
    __syncthreads();
    if (!s_last) return;
    __threadfence();

    // ---- H: per-image global top-200 (bucket) ----
    for (int i = tid; i < FBINS; i += 512) hist[i] = 0;
    if (tid == 0) { s_ftb = -1; s_sel = 0; }
    if (tid < NFG) skc[tid] = g_kcount[b * NFG + tid];
    __syncthreads();

    for (int idx = tid; idx < NFG * TOPK; idx += 512) {
        int c = idx / TOPK, slot = idx - c * TOPK;
        if (slot < skc[c]) {
            unsigned bits = __float_as_uint(g_kscore[(b * NFG + c) * TOPK + slot]);
            atomicAdd(&hist[finebin(bits)], 1);
        }
    }
    __syncthreads();

    int total2 = suffix_scan_2048(hist, tid, sfx, &above);
    {
        int need = total2 < TOPK ? total2 : TOPK;
        if (need > 0) {
#pragma unroll
            for (int q = 0; q < 4; ++q) {
                int nxt = (q < 3) ? sfx[q + 1] : above;
                if (sfx[q] >= need && nxt < need) {
                    s_ftb = tid * 4 + q;
                    s_sel = sfx[q];
                }
            }
        }
    }
    __syncthreads();
    const int ftb2 = s_ftb;
    int count2 = s_sel; if (count2 > TOPK) count2 = TOPK; if (count2 > 512) count2 = 512;

    if (ftb2 >= 0) {
        for (int idx = tid; idx < NFG * TOPK; idx += 512) {
            int c = idx / TOPK, slot = idx - c * TOPK;
            if (slot < skc[c]) {
                unsigned bits = __float_as_uint(g_kscore[(b * NFG + c) * TOPK + slot]);
                int fb = (int)finebin(bits);
                if (fb >= ftb2) {
                    int pos = atomicAdd(&hist[fb], 1);
                    if (pos < 512)
                        dest[pos] = ((unsigned long long)bits << 32) |
                                    (0xFFFFFFFFu - (unsigned)(c * 256 + slot));
                }
            }
        }
        __syncthreads();
        for (int fb = ftb2 + tid; fb < FBINS; fb += 512) {
            int lo = (fb == FBINS - 1) ? 0 : hist[fb + 1];
            int hi = hist[fb];
            if (hi > 512) hi = 512;
            if (lo > hi) lo = hi;
            for (int x = lo + 1; x < hi; ++x) {
                unsigned long long key = dest[x];
                int y = x - 1;
                while (y >= lo && dest[y] < key) { dest[y + 1] = dest[y]; --y; }
                dest[y + 1] = key;
            }
        }
        __syncthreads();
    }

    if (tid < TOPK) {
        float b0 = 0.f, b1 = 0.f, b2 = 0.f, b3 = 0.f, sco = 0.f, lab = 0.f;
        if (tid < count2) {
            unsigned long long key = dest[tid];
            unsigned code = 0xFFFFFFFFu - (unsigned)(key & 0xFFFFFFFFu);
            int c    = (int)(code >> 8);
            int slot = (int)(code & 255u);
            float4 kb = g_kbox[(b * NFG + c) * TOPK + slot];
            sco = __uint_as_float((unsigned)(key >> 32));
            b0 = kb.x; b1 = kb.y; b2 = kb.z; b3 = kb.w;
            lab = (float)(c + 1);
        }
        out[(b * TOPK + tid) * 4 + 0] = b0;
        out[(b * TOPK + tid) * 4 + 1] = b1;
        out[(b * TOPK + tid) * 4 + 2] = b2;
        out[(b * TOPK + tid) * 4 + 3] = b3;
        out[BATCH * TOPK * 4 + b * TOPK + tid] = sco;
        out[BATCH * TOPK * 5 + b * TOPK + tid] = lab;
    }
}

// ============================================================
extern "C" void kernel_launch(void* const* d_in, const int* in_sizes, int n_in,
                              void* d_out, int out_size) {
    const float* cls  = (const float*)d_in[0];  // [8, 8732, 21]
    const float* loc  = (const float*)d_in[1];  // [8, 8732, 4]
    const float* anch = (const float*)d_in[2];  // [8732, 4]
    float* out = (float*)d_out;

    prep_kernel<<<TR_BLOCKS, 256>>>(cls);
    nms_kernel<<<BATCH * NFG, 512>>>(loc, anch, out);
}

// round 14
// speedup vs baseline: 1.1137x; 1.1137x over previous
#include <cuda_runtime.h>
#include <math.h>

#define BATCH   8
#define NA      8732
#define NAP     8736
#define NC      21
#define NFG     20
#define TOPK    200
#define PRE     1024
#define DCAP    1280
#define FBINS   2048
#define FSH     12
#define BASEB   0x3F000000u
#define CONF_T  0.5f
#define FULLM   0xFFFFFFFFu

// Exact midpoint for  div.rn.f32(inter,union) > 0.45f :
// 0.45f = 0x3EE66666 (even mantissa); ulp = 2^-25; midpoint = c + 2^-26.
// (double)inter and MID*(double)union are exact -> bit-identical decisions.
#define IOU_MID (0.449999988079071044921875 + 1.490116119384765625e-8)

// ---- scratch (static __device__, allocation-free) ----
__device__ float    g_clsT[BATCH * NFG * NAP];   // transposed scores; pad stays 0
__device__ float    g_kscore[BATCH * NFG * TOPK];
__device__ float4   g_kbox[BATCH * NFG * TOPK];
__device__ int      g_kcount[BATCH * NFG];
__device__ unsigned g_done[BATCH];               // wrap counters (stay 0 after run)

#define TR_TILE   128
#define TR_TPB    ((NA + TR_TILE - 1) / TR_TILE)   // 69
#define TR_BLOCKS (BATCH * TR_TPB)

// Branchless, division-free, BIT-EXACT equivalent of the reference IoU test
// (measured fastest variant, R11).
__device__ __forceinline__ bool iou_hit(float4 p, float pa, float4 q, float qa) {
    float w = fminf(p.z, q.z) - fmaxf(p.x, q.x) + 1.0f;
    float h = fminf(p.w, q.w) - fmaxf(p.y, q.y) + 1.0f;
    float inter = fmaxf(w, 0.0f) * fmaxf(h, 0.0f);
    float uni = pa + qa - inter;
    return (double)inter > IOU_MID * (double)uni;
}

__device__ __forceinline__ unsigned finebin(unsigned bits) {
    unsigned fb = (bits - BASEB) >> FSH;
    return fb > (FBINS - 1u) ? (FBINS - 1u) : fb;
}

// Block suffix-scan over FBINS bins (512 threads, 4 consecutive bins each).
__device__ __forceinline__ int suffix_scan_2048(int* hist, int tid, int* sfx,
                                                int* above_out) {
    __shared__ int ws[16];
    __shared__ int s_total;
    const int lane = tid & 31, wid = tid >> 5;
    int b4 = tid * 4;
    int h0 = hist[b4], h1 = hist[b4 + 1], h2 = hist[b4 + 2], h3 = hist[b4 + 3];
    sfx[3] = h3; sfx[2] = h2 + sfx[3]; sfx[1] = h1 + sfx[2]; sfx[0] = h0 + sfx[1];
    int T = sfx[0], S = T;
#pragma unroll
    for (int off = 1; off < 32; off <<= 1) {
        int v = __shfl_down_sync(FULLM, S, off);
        if (lane + off < 32) S += v;
    }
    if (lane == 0) ws[wid] = S;
    __syncthreads();
    if (tid < 16) {
        int W = ws[tid];
#pragma unroll
        for (int off = 1; off < 16; off <<= 1) {
            int v = __shfl_down_sync(0x0000FFFFu, W, off);
            if (tid + off < 16) W += v;
        }
        ws[tid] = W;
        if (tid == 0) s_total = W;
    }
    __syncthreads();
    int above = ((wid < 15) ? ws[wid + 1] : 0) + (S - T);
    sfx[0] += above; sfx[1] += above; sfx[2] += above; sfx[3] += above;
    hist[b4]     = sfx[1];
    hist[b4 + 1] = sfx[2];
    hist[b4 + 2] = sfx[3];
    hist[b4 + 3] = above;
    *above_out = above;
    return s_total;
}

// ============================================================
// Kernel 1: transpose cls [b][a][c] -> g_clsT [b][c][a] (coalesced).
// ============================================================
__global__ void prep_kernel(const float* __restrict__ cls) {
    __shared__ float sh[TR_TILE * NC];
    int t = blockIdx.x;
    int b = t / TR_TPB, tile = t % TR_TPB;
    int a0 = tile * TR_TILE;
    int n = NA - a0; if (n > TR_TILE) n = TR_TILE;
    const float* src = cls + ((size_t)(b * NA + a0)) * NC;
    for (int i = threadIdx.x; i < n * NC; i += 256) sh[i] = src[i];
    __syncthreads();
    int half = threadIdx.x >> 7;
    int t2 = threadIdx.x & 127;
    if (t2 < n) {
        for (int c = half * 10; c < half * 10 + 10; ++c)
            g_clsT[((size_t)(b * NFG + c)) * NAP + a0 + t2] = sh[t2 * NC + c + 1];
    }
}

// ============================================================
// Kernel 2: bucket top-1024 + compacted fixpoint greedy NMS; last CTA
// per image also performs the per-image global top-200 (fused).
// ============================================================
__global__ __launch_bounds__(512, 2) void nms_kernel(const float* __restrict__ loc,
                                                     const float* __restrict__ anch,
                                                     float* __restrict__ out) {
    const int bc  = blockIdx.x;
    const int b   = bc / NFG;
    const int c20 = bc % NFG;
    const int tid = threadIdx.x;

    __shared__ __align__(16) int histbuf[FBINS];             // 8KB
    __shared__ __align__(16) unsigned long long dest[DCAP];  // 10KB
    __shared__ __align__(16) float4 sbox[PRE];               // 16KB
    __shared__ float  sar[PRE], ssc[PRE];                    // 8KB
    __shared__ short  cidx[256];                             // compacted->tile idx
    __shared__ unsigned kw[8], pf[8];
    __shared__ int psum[8];
    __shared__ int skc[NFG];
    __shared__ int s_fl[2];
    __shared__ int s_ftb, s_sel, s_last, s_ma;

    int* hist = histbuf;
    unsigned* colmask = (unsigned*)histbuf;
    float4* lbox = (float4*)dest;
    float*  lar  = (float*)(dest + 512);

    for (int i = tid; i < FBINS; i += 512) hist[i] = 0;
    if (tid == 0) { s_ftb = -1; s_sel = 0; }
    __syncthreads();

    const float4* scol4 = reinterpret_cast<const float4*>(
        g_clsT + ((size_t)(b * NFG + c20)) * NAP);

    // ---- A: fine histogram, vectorized float4 (pad scores are 0) ----
    for (int v = tid; v < NAP / 4; v += 512) {
        float4 s4 = scol4[v];
        if (s4.x > CONF_T) atomicAdd(&hist[finebin(__float_as_uint(s4.x))], 1);
        if (s4.y > CONF_T) atomicAdd(&hist[finebin(__float_as_uint(s4.y))], 1);
        if (s4.z > CONF_T) atomicAdd(&hist[finebin(__float_as_uint(s4.z))], 1);
        if (s4.w > CONF_T) atomicAdd(&hist[finebin(__float_as_uint(s4.w))], 1);
    }
    __syncthreads();

    // ---- B: suffix scan; unique-boundary threshold (no atomics) ----
    int sfx[4], above;
    int total = suffix_scan_2048(hist, tid, sfx, &above);
    {
        int need = total < PRE ? total : PRE;
        if (need > 0) {
#pragma unroll
            for (int q = 0; q < 4; ++q) {
                int nxt = (q < 3) ? sfx[q + 1] : above;
                if (sfx[q] >= need && nxt < need) {
                    s_ftb = tid * 4 + q;
                    s_sel = sfx[q];
                }
            }
        }
    }
    __syncthreads();
    const int ftb = s_ftb;
    int count = s_sel; if (count > PRE) count = PRE; if (count > DCAP) count = DCAP;

    // ---- C: scatter to exact positions + per-bin tie sort ----
    if (ftb >= 0) {
        for (int v = tid; v < NAP / 4; v += 512) {
            float4 s4 = scol4[v];
            float sv[4] = {s4.x, s4.y, s4.z, s4.w};
#pragma unroll
            for (int k = 0; k < 4; ++k) {
                if (sv[k] > CONF_T) {
                    unsigned bits = __float_as_uint(sv[k]);
                    int fb = (int)finebin(bits);
                    if (fb >= ftb) {
                        int pos = atomicAdd(&hist[fb], 1);
                        if (pos < DCAP)
                            dest[pos] = ((unsigned long long)bits << 32) |
                                        (unsigned)(65535 - (4 * v + k));
                    }
                }
            }
        }
        __syncthreads();
        for (int fb = ftb + tid; fb < FBINS; fb += 512) {
            int lo = (fb == FBINS - 1) ? 0 : hist[fb + 1];
            int hi = hist[fb];
            if (hi > DCAP) hi = DCAP;
            if (lo > hi) lo = hi;
            for (int x = lo + 1; x < hi; ++x) {
                unsigned long long key = dest[x];
                int y = x - 1;
                while (y >= lo && dest[y] < key) { dest[y + 1] = dest[y]; --y; }
                dest[y + 1] = key;
            }
        }
        __syncthreads();
    }

    // ---- E: decode candidate boxes best-first ----
    const float4* loc4  = reinterpret_cast<const float4*>(loc);
    const float4* anch4 = reinterpret_cast<const float4*>(anch);
#pragma unroll
    for (int t = 0; t < 2; ++t) {
        int r = tid + t * 512;
        if (r < count) {
            unsigned long long key = dest[r];
            int a = 65535 - (int)(key & 0xFFFFu);
            float4 l  = loc4[b * NA + a];
            float4 an = anch4[a];
            float cx = an.x + l.x * 0.1f * an.z;
            float cy = an.y + l.y * 0.1f * an.w;
            float w  = an.z * expf(l.z * 0.2f);
            float h  = an.w * expf(l.w * 0.2f);
            float x1 = cx - w * 0.5f;
            float y1 = cy - h * 0.5f;
            float4 bb;
            bb.x = fminf(fmaxf(x1 * 300.0f, 0.0f), 299.0f);
            bb.y = fminf(fmaxf(y1 * 300.0f, 0.0f), 299.0f);
            bb.z = fminf(fmaxf((x1 + w) * 300.0f, 0.0f), 299.0f);
            bb.w = fminf(fmaxf((y1 + h) * 300.0f, 0.0f), 299.0f);
            sbox[r] = bb;
            sar[r] = (bb.z - bb.x + 1.0f) * (bb.w - bb.y + 1.0f);
            ssc[r] = __uint_as_float((unsigned)(key >> 32));
        }
    }
    __syncthreads();   // hist & dest dead; overlays live

    // ---- F: tiled greedy NMS: prefilter -> compact -> mask -> fixpoint ----
    int nL = 0;
    for (int base = 0; base < count && nL < TOPK; base += 256) {
        int m = count - base; if (m > 256) m = 256;
        if (tid < 8) pf[tid] = 0u;
        __syncthreads();
        // prefilter vs kept list: 2 threads per candidate, 4-wide batched
        if (base > 0 && nL > 0) {
            int i = tid >> 1, half = tid & 1;
            if (i < m) {
                float4 bb = sbox[base + i];
                float ab = sar[base + i];
                bool dead = false;
                int k = half;
                for (; k + 6 < nL; k += 8) {
                    dead |= iou_hit(lbox[k],     lar[k],     bb, ab);
                    dead |= iou_hit(lbox[k + 2], lar[k + 2], bb, ab);
                    dead |= iou_hit(lbox[k + 4], lar[k + 4], bb, ab);
                    dead |= iou_hit(lbox[k + 6], lar[k + 6], bb, ab);
                }
                for (; k < nL; k += 2)
                    dead |= iou_hit(lbox[k], lar[k], bb, ab);
                if (dead) atomicOr(&pf[i >> 5], 1u << (i & 31));
            }
        }
        __syncthreads();
        // order-preserving compaction of alive candidates -> cidx[0..ma)
        if (tid < 8) {
            int lo = tid * 32;
            unsigned valid;
            if (m >= lo + 32)      valid = FULLM;
            else if (m <= lo)      valid = 0u;
            else                   valid = (1u << (m - lo)) - 1u;
            unsigned aw = valid & ~pf[tid];
            pf[tid] = aw;                      // reuse pf as alive words
        }
        __syncthreads();
        if (tid < 8) {
            int s = 0;
            for (int w2 = 0; w2 < tid; ++w2) s += __popc(pf[w2]);
            psum[tid] = s;
            if (tid == 7) s_ma = s + __popc(pf[7]);
        }
        __syncthreads();
        const int ma = s_ma;
        if (ma > 0) {
            if (tid < m && ((pf[tid >> 5] >> (tid & 31)) & 1u)) {
                int r = psum[tid >> 5] +
                        __popc(pf[tid >> 5] & ((1u << (tid & 31)) - 1u));
                cidx[r] = (short)tid;
            }
            __syncthreads();
            // triangular IoU mask over COMPACTED indices
            const int words = (ma + 31) >> 5;
#pragma unroll
            for (int q = 0; q < 4; ++q) {
                int jid = tid + q * 512;
                int i = jid & 255, w = jid >> 8;
                int jn = i - w * 32; if (jn > 32) jn = 32;
                if (i < ma && w < words) {
                    if (jn > 0) {
                        int ti = base + cidx[i];
                        float4 bi = sbox[ti];
                        float ai = sar[ti];
                        unsigned bits = 0u;
                        int j0 = w * 32;
                        int l = 0;
                        for (; l + 4 <= jn; l += 4) {
                            int a0 = base + cidx[j0 + l];
                            int a1 = base + cidx[j0 + l + 1];
                            int a2 = base + cidx[j0 + l + 2];
                            int a3 = base + cidx[j0 + l + 3];
                            if (iou_hit(bi, ai, sbox[a0], sar[a0])) bits |= 1u << l;
                            if (iou_hit(bi, ai, sbox[a1], sar[a1])) bits |= 1u << (l + 1);
                            if (iou_hit(bi, ai, sbox[a2], sar[a2])) bits |= 1u << (l + 2);
                            if (iou_hit(bi, ai, sbox[a3], sar[a3])) bits |= 1u << (l + 3);
                        }
                        for (; l < jn; ++l) {
                            int aj = base + cidx[j0 + l];
                            if (iou_hit(bi, ai, sbox[aj], sar[aj]))
                                bits |= 1u << l;
                        }
                        colmask[i * 8 + w] = bits;
                    } else {
                        colmask[i * 8 + w] = 0u;
                    }
                }
            }
            __syncthreads();
            if (tid < 8) {
                int lo = tid * 32;
                unsigned valid;
                if (ma >= lo + 32)      valid = FULLM;
                else if (ma <= lo)      valid = 0u;
                else                    valid = (1u << (ma - lo)) - 1u;
                kw[tid] = valid;
            }
            if (tid == 0) { s_fl[0] = 0; s_fl[1] = 0; }
            // cache own colmask row in registers
            unsigned cm[8];
            int pre_ok = (tid < ma);
            __syncthreads();
            if (pre_ok) {
#pragma unroll
                for (int w = 0; w < 8; ++w) cm[w] = colmask[tid * 8 + w];
            }
            // fixpoint: 2 barriers per sweep, parity convergence flags
            int p = 0;
            for (;;) {
                int alive = 0;
                if (pre_ok) {
                    unsigned acc = (cm[0] & kw[0]) | (cm[1] & kw[1]) |
                                   (cm[2] & kw[2]) | (cm[3] & kw[3]) |
                                   (cm[4] & kw[4]) | (cm[5] & kw[5]) |
                                   (cm[6] & kw[6]) | (cm[7] & kw[7]);
                    alive = (acc == 0u);
                }
                __syncthreads();
                unsigned nw = __ballot_sync(FULLM, alive);
                if (tid < 256 && (tid & 31) == 0) {
                    if (nw != kw[tid >> 5]) s_fl[p] = 1;
                    kw[tid >> 5] = nw;
                }
                if (tid == 0) s_fl[p ^ 1] = 0;
                __syncthreads();
                if (!s_fl[p]) break;
                p ^= 1;
            }
            if (tid < 8) {
                int s = 0;
                for (int w2 = 0; w2 < tid; ++w2) s += __popc(kw[w2]);
                psum[tid] = s;
            }
            __syncthreads();
            int nk = psum[7] + __popc(kw[7]);
            int take = TOPK - nL; if (take > nk) take = nk;
            if (tid < ma && ((kw[tid >> 5] >> (tid & 31)) & 1u)) {
                int r = psum[tid >> 5] +
                        __popc(kw[tid >> 5] & ((1u << (tid & 31)) - 1u));
                if (r < take) {
                    int slot = nL + r;
                    int src = base + cidx[tid];
                    int gb = bc * TOPK + slot;
                    g_kscore[gb] = ssc[src];
                    g_kbox[gb]   = sbox[src];
                    lbox[slot]   = sbox[src];
                    lar[slot]    = sar[src];
                }
            }
            nL += take;
        }
        __syncthreads();
    }
    if (tid == 0) g_kcount[bc] = nL;

    // ---- G: completion counter; last CTA of image runs the global top-200 ----
    if (tid == 0) {
        __threadfence();
        unsigned old = atomicInc(&g_done[b], NFG - 1);
        s_last = (old == NFG - 1);
    }
    __syncthreads();
    if (!s_last) return;
    __threadfence();

    // ---- H: per-image global top-200 (bucket) ----
    for (int i = tid; i < FBINS; i += 512) hist[i] = 0;
    if (tid == 0) { s_ftb = -1; s_sel = 0; }
    if (tid < NFG) skc[tid] = g_kcount[b * NFG + tid];
    __syncthreads();

    for (int idx = tid; idx < NFG * TOPK; idx += 512) {
        int c = idx / TOPK, slot = idx - c * TOPK;
        if (slot < skc[c]) {
            unsigned bits = __float_as_uint(g_kscore[(b * NFG + c) * TOPK + slot]);
            atomicAdd(&hist[finebin(bits)], 1);
        }
    }
    __syncthreads();

    int total2 = suffix_scan_2048(hist, tid, sfx, &above);
    {
        int need = total2 < TOPK ? total2 : TOPK;
        if (need > 0) {
#pragma unroll
            for (int q = 0; q < 4; ++q) {
                int nxt = (q < 3) ? sfx[q + 1] : above;
                if (sfx[q] >= need && nxt < need) {
                    s_ftb = tid * 4 + q;
                    s_sel = sfx[q];
                }
            }
        }
    }
    __syncthreads();
    const int ftb2 = s_ftb;
    int count2 = s_sel; if (count2 > TOPK) count2 = TOPK; if (count2 > 512) count2 = 512;

    if (ftb2 >= 0) {
        for (int idx = tid; idx < NFG * TOPK; idx += 512) {
            int c = idx / TOPK, slot = idx - c * TOPK;
            if (slot < skc[c]) {
                unsigned bits = __float_as_uint(g_kscore[(b * NFG + c) * TOPK + slot]);
                int fb = (int)finebin(bits);
                if (fb >= ftb2) {
                    int pos = atomicAdd(&hist[fb], 1);
                    if (pos < 512)
                        dest[pos] = ((unsigned long long)bits << 32) |
                                    (0xFFFFFFFFu - (unsigned)(c * 256 + slot));
                }
            }
        }
        __syncthreads();
        for (int fb = ftb2 + tid; fb < FBINS; fb += 512) {
            int lo = (fb == FBINS - 1) ? 0 : hist[fb + 1];
            int hi = hist[fb];
            if (hi > 512) hi = 512;
            if (lo > hi) lo = hi;
            for (int x = lo + 1; x < hi; ++x) {
                unsigned long long key = dest[x];
                int y = x - 1;
                while (y >= lo && dest[y] < key) { dest[y + 1] = dest[y]; --y; }
                dest[y + 1] = key;
            }
        }
        __syncthreads();
    }

    if (tid < TOPK) {
        float b0 = 0.f, b1 = 0.f, b2 = 0.f, b3 = 0.f, sco = 0.f, lab = 0.f;
        if (tid < count2) {
            unsigned long long key = dest[tid];
            unsigned code = 0xFFFFFFFFu - (unsigned)(key & 0xFFFFFFFFu);
            int c    = (int)(code >> 8);
            int slot = (int)(code & 255u);
            float4 kb = g_kbox[(b * NFG + c) * TOPK + slot];
            sco = __uint_as_float((unsigned)(key >> 32));
            b0 = kb.x; b1 = kb.y; b2 = kb.z; b3 = kb.w;
            lab = (float)(c + 1);
        }
        out[(b * TOPK + tid) * 4 + 0] = b0;
        out[(b * TOPK + tid) * 4 + 1] = b1;
        out[(b * TOPK + tid) * 4 + 2] = b2;
        out[(b * TOPK + tid) * 4 + 3] = b3;
        out[BATCH * TOPK * 4 + b * TOPK + tid] = sco;
        out[BATCH * TOPK * 5 + b * TOPK + tid] = lab;
    }
}

// ============================================================
extern "C" void kernel_launch(void* const* d_in, const int* in_sizes, int n_in,
                              void* d_out, int out_size) {
    const float* cls  = (const float*)d_in[0];  // [8, 8732, 21]
    const float* loc  = (const float*)d_in[1];  // [8, 8732, 4]
    const float* anch = (const float*)d_in[2];  // [8732, 4]
    float* out = (float*)d_out;

    prep_kernel<<<TR_BLOCKS, 256>>>(cls);
    nms_kernel<<<BATCH * NFG, 512>>>(loc, anch, out);
}